// round 7
// baseline (speedup 1.0000x reference)
#include <cuda_runtime.h>
#include <cstdint>

// ---------------- problem constants ----------------
#define B      128
#define D      768
#define POOL   100
#define LG     6
#define LE     6
#define GLEN   5
#define ELEN   20
#define H      12
#define HD     64
#define TOPK   5

// Output rows: one row = HD floats = 16 float4 = 256 bytes.
#define G_ROWS     (LG*2*B*H*GLEN)              // 92,160
#define E_ROWS     (LE*2*B*H*(TOPK*ELEN))       // 1,843,200
#define G_PAIRS    (G_ROWS*8)                   // 737,280
#define E_PAIRS    (E_ROWS*8)                   // 14,745,600

#define THREADS    256
#define SEL_BLOCKS 128
#define G_BLOCKS   (G_PAIRS/THREADS)            // 2,880 (exact)
#define E_BLOCKS   (E_PAIRS/THREADS)            // 57,600 (exact)
#define TOTAL_BLOCKS (SEL_BLOCKS + G_BLOCKS + E_BLOCKS)

// scratch (no cudaMalloc allowed)
__device__ int d_idx[B * TOPK];
__device__ int d_flag;            // reset to 0 via cudaMemsetAsync each call

// ---------------------------------------------------------------------------
// Single fused kernel, register-capped for full occupancy on the writer
// branches (launch_bounds minBlocks=8 -> <=32 regs; selection branch may
// spill to local, which is irrelevant at 128/60608 blocks).
//  blocks [0,128):            selection (wave-1 resident; sets d_flag)
//  blocks [128,128+2880):     g-region writer (independent)
//  blocks [128+2880,...):     e-region writer (flag already set when these
//                             are scheduled; spin is nominal)
// ---------------------------------------------------------------------------
__global__ __launch_bounds__(THREADS, 8) void dual_prompt_kernel(
        const float4* __restrict__ query4,
        const float4* __restrict__ keys4,
        const float4* __restrict__ g4,
        const float4* __restrict__ pool4,
        float4* __restrict__ out4) {
    const int blk = blockIdx.x;

    if (blk >= SEL_BLOCKS + G_BLOCKS) {
        // ===== e region (hot path first): out[ld,b,h,m,:] =
        //       pool[idx[b][m/ELEN], ld, m%ELEN, h, :]
        if (threadIdx.x == 0) {
            while (atomicAdd(&d_flag, 0) < SEL_BLOCKS) { }
        }
        __syncthreads();

        int gid = (blk - SEL_BLOCKS - G_BLOCKS) * THREADS + threadIdx.x; // < E_PAIRS exact
        const int c4h = gid & 7;
        const int row = gid >> 3;              // 0..E_ROWS-1

        // row = ((ld*B + b)*H + h)*100 + m
        int v  = row;
        int m  = v % (TOPK * ELEN); v /= (TOPK * ELEN);
        int h  = v % H;             v /= H;
        int b  = v & 127;           v >>= 7;
        int ld = v;                            // 0..11
        int k  = m / ELEN;
        int e  = m - k * ELEN;
        int p  = __ldcg(&d_idx[b * TOPK + k]);  // L2-coherent read

        const float4* src = &pool4[((((p * 12 + ld) * ELEN + e) * H + h) << 4) + c4h];
        float4 v0 = __ldg(src);
        float4 v1 = __ldg(src + 8);

        float4* dst = out4 + (((long long)G_ROWS + row) << 4) + c4h;
        __stcs(dst,     v0);
        __stcs(dst + 8, v1);
    } else if (blk >= SEL_BLOCKS) {
        // ===== g region: out[ld,b,h,gl,:] = g_prompt[ld,gl,h,:] =====
        int gid = (blk - SEL_BLOCKS) * THREADS + threadIdx.x;   // < G_PAIRS exact
        const int c4h = gid & 7;
        const int row = gid >> 3;
        int v  = row;
        int gl = v % GLEN; v /= GLEN;
        int h  = v % H;    v /= H;
        v >>= 7;                               // drop b
        int ld = v;                            // 0..11
        const float4* src = &g4[(((ld * GLEN + gl) * H + h) << 4) + c4h];
        float4 v0 = __ldg(src);
        float4 v1 = __ldg(src + 8);
        float4* dst = out4 + ((long long)row << 4) + c4h;
        __stcs(dst,     v0);
        __stcs(dst + 8, v1);
    } else {
        // ===== selection: one query row per block, 8 warps =====
        const int b    = blk;
        const int t    = threadIdx.x;
        const int warp = t >> 5;
        const int lane = t & 31;

        __shared__ float sims[POOL];

        const float4* qr = query4 + (size_t)b * (D / 4);
        float4 fq[6];
        #pragma unroll
        for (int j = 0; j < 6; j++) fq[j] = __ldg(&qr[lane + 32 * j]);

        // qn dropped: positive per-row constant, ranking-invariant.
        for (int p = warp; p < POOL; p += 8) {
            const float4* kr = keys4 + (size_t)p * (D / 4);
            float dot = 0.f, kk = 0.f;
            #pragma unroll
            for (int j = 0; j < 6; j++) {
                float4 kv = __ldg(&kr[lane + 32 * j]);
                dot = fmaf(fq[j].x, kv.x, dot);
                dot = fmaf(fq[j].y, kv.y, dot);
                dot = fmaf(fq[j].z, kv.z, dot);
                dot = fmaf(fq[j].w, kv.w, dot);
                kk  = fmaf(kv.x, kv.x, kk);
                kk  = fmaf(kv.y, kv.y, kk);
                kk  = fmaf(kv.z, kv.z, kk);
                kk  = fmaf(kv.w, kv.w, kk);
            }
            #pragma unroll
            for (int o = 16; o > 0; o >>= 1) {
                dot += __shfl_xor_sync(0xFFFFFFFFu, dot, o);
                kk  += __shfl_xor_sync(0xFFFFFFFFu, kk,  o);
            }
            if (lane == 0) {
                float kn = fmaxf(sqrtf(kk), 1e-12f);
                sims[p] = dot / kn;
            }
        }
        __syncthreads();

        // warp 0: parallel top-5 argmax, tie-break = lowest index (jax order)
        if (warp == 0) {
            #pragma unroll
            for (int k = 0; k < TOPK; k++) {
                float best = -3.0e38f;
                int   bi   = POOL;
                #pragma unroll
                for (int j = 0; j < 4; j++) {
                    int p = lane + 32 * j;
                    if (p < POOL) {
                        float v = sims[p];
                        if (v > best) { best = v; bi = p; }
                    }
                }
                #pragma unroll
                for (int o = 16; o > 0; o >>= 1) {
                    float ov = __shfl_xor_sync(0xFFFFFFFFu, best, o);
                    int   oi = __shfl_xor_sync(0xFFFFFFFFu, bi,   o);
                    if (ov > best || (ov == best && oi < bi)) { best = ov; bi = oi; }
                }
                if (lane == 0) {
                    d_idx[b * TOPK + k] = bi;
                    sims[bi] = -3.0e38f;
                }
                __syncwarp();
            }
            if (lane == 0) {
                __threadfence();               // publish d_idx before flag
                atomicAdd(&d_flag, 1);
            }
        }
    }
}

// ---------------------------------------------------------------------------
extern "C" void kernel_launch(void* const* d_in, const int* in_sizes, int n_in,
                              void* d_out, int out_size) {
    const float* query = (const float*)d_in[0];
    const float* gprm  = (const float*)d_in[1];
    const float* pool  = (const float*)d_in[2];
    const float* keys  = (const float*)d_in[3];
    float* out = (float*)d_out;

    // reset in-kernel dependency flag (graph-capturable memset node)
    void* flag_addr = nullptr;
    cudaGetSymbolAddress(&flag_addr, d_flag);
    cudaMemsetAsync(flag_addr, 0, sizeof(int));

    dual_prompt_kernel<<<TOTAL_BLOCKS, THREADS>>>(
        (const float4*)query, (const float4*)keys,
        (const float4*)gprm, (const float4*)pool, (float4*)out);
}

// round 8
// speedup vs baseline: 1.3065x; 1.3065x over previous
#include <cuda_runtime.h>
#include <cstdint>

// ---------------- problem constants ----------------
#define B      128
#define D      768
#define POOL   100
#define LG     6
#define LE     6
#define GLEN   5
#define ELEN   20
#define H      12
#define HD     64
#define TOPK   5

// Output rows: one row = HD floats = 16 float4 = 256 bytes.
#define G_ROWS     (LG*2*B*H*GLEN)              // 92,160
#define E_ROWS     (LE*2*B*H*(TOPK*ELEN))       // 1,843,200
#define TOTAL_ROWS (G_ROWS + E_ROWS)            // 1,935,360
#define TOTAL_PAIRS (TOTAL_ROWS * 8)            // 15,482,880

// scratch for selected indices (no cudaMalloc allowed)
__device__ int d_idx[B * TOPK];

// ---------------------------------------------------------------------------
// Kernel 1: cosine-sim + top-5 selection, latency-optimized.
// One block per query row, 1024 threads = 32 warps. Each warp owns only
// 3-4 pool entries and processes them TOGETHER in the inner loop: all
// entries' key loads per j-step are independent (MLP ~12-16), so the cold
// DRAM latency is paid ~once instead of once per entry.
// qn dropped (positive per-row constant => ranking-invariant).
// Tie-break = lowest index, matching jax.lax.top_k.
// ---------------------------------------------------------------------------
__global__ __launch_bounds__(1024) void select_topk_kernel(
        const float4* __restrict__ query4,
        const float4* __restrict__ keys4) {
    const int b    = blockIdx.x;
    const int t    = threadIdx.x;
    const int warp = t >> 5;
    const int lane = t & 31;

    __shared__ float sims[POOL];

    // preload query row: 192 float4, lane-strided, 6 per lane
    const float4* qr = query4 + (size_t)b * (D / 4);
    float4 fq[6];
    #pragma unroll
    for (int j = 0; j < 6; j++) fq[j] = __ldg(&qr[lane + 32 * j]);

    // warp's entries: p = warp, warp+32, warp+64 (+96 for warps 0..3)
    const int p0 = warp;
    const int p1 = warp + 32;
    const int p2 = warp + 64;
    const int p3 = warp + 96;               // valid only if < POOL (warps 0..3)
    const bool has4 = (p3 < POOL);

    const float4* k0 = keys4 + (size_t)p0 * (D / 4);
    const float4* k1 = keys4 + (size_t)p1 * (D / 4);
    const float4* k2 = keys4 + (size_t)p2 * (D / 4);
    const float4* k3 = keys4 + (size_t)(has4 ? p3 : p0) * (D / 4);

    float d0 = 0.f, d1 = 0.f, d2 = 0.f, d3 = 0.f;
    float n0 = 0.f, n1 = 0.f, n2 = 0.f, n3 = 0.f;

    #pragma unroll
    for (int j = 0; j < 6; j++) {
        const int off = lane + 32 * j;
        float4 a = __ldg(&k0[off]);
        float4 c = __ldg(&k1[off]);
        float4 e = __ldg(&k2[off]);
        float4 g = __ldg(&k3[off]);
        float4 q = fq[j];
        d0 = fmaf(q.x, a.x, d0); d0 = fmaf(q.y, a.y, d0);
        d0 = fmaf(q.z, a.z, d0); d0 = fmaf(q.w, a.w, d0);
        n0 = fmaf(a.x, a.x, n0); n0 = fmaf(a.y, a.y, n0);
        n0 = fmaf(a.z, a.z, n0); n0 = fmaf(a.w, a.w, n0);
        d1 = fmaf(q.x, c.x, d1); d1 = fmaf(q.y, c.y, d1);
        d1 = fmaf(q.z, c.z, d1); d1 = fmaf(q.w, c.w, d1);
        n1 = fmaf(c.x, c.x, n1); n1 = fmaf(c.y, c.y, n1);
        n1 = fmaf(c.z, c.z, n1); n1 = fmaf(c.w, c.w, n1);
        d2 = fmaf(q.x, e.x, d2); d2 = fmaf(q.y, e.y, d2);
        d2 = fmaf(q.z, e.z, d2); d2 = fmaf(q.w, e.w, d2);
        n2 = fmaf(e.x, e.x, n2); n2 = fmaf(e.y, e.y, n2);
        n2 = fmaf(e.z, e.z, n2); n2 = fmaf(e.w, e.w, n2);
        d3 = fmaf(q.x, g.x, d3); d3 = fmaf(q.y, g.y, d3);
        d3 = fmaf(q.z, g.z, d3); d3 = fmaf(q.w, g.w, d3);
        n3 = fmaf(g.x, g.x, n3); n3 = fmaf(g.y, g.y, n3);
        n3 = fmaf(g.z, g.z, n3); n3 = fmaf(g.w, g.w, n3);
    }

    #pragma unroll
    for (int o = 16; o > 0; o >>= 1) {
        d0 += __shfl_xor_sync(0xFFFFFFFFu, d0, o);
        n0 += __shfl_xor_sync(0xFFFFFFFFu, n0, o);
        d1 += __shfl_xor_sync(0xFFFFFFFFu, d1, o);
        n1 += __shfl_xor_sync(0xFFFFFFFFu, n1, o);
        d2 += __shfl_xor_sync(0xFFFFFFFFu, d2, o);
        n2 += __shfl_xor_sync(0xFFFFFFFFu, n2, o);
        d3 += __shfl_xor_sync(0xFFFFFFFFu, d3, o);
        n3 += __shfl_xor_sync(0xFFFFFFFFu, n3, o);
    }

    if (lane == 0) {
        sims[p0] = d0 / fmaxf(sqrtf(n0), 1e-12f);
        sims[p1] = d1 / fmaxf(sqrtf(n1), 1e-12f);
        sims[p2] = d2 / fmaxf(sqrtf(n2), 1e-12f);
        if (has4) sims[p3] = d3 / fmaxf(sqrtf(n3), 1e-12f);
    }
    __syncthreads();

    // warp 0: parallel top-5 argmax, tie-break = lowest index
    if (warp == 0) {
        #pragma unroll
        for (int k = 0; k < TOPK; k++) {
            float best = -3.0e38f;
            int   bi   = POOL;
            #pragma unroll
            for (int j = 0; j < 4; j++) {
                int p = lane + 32 * j;
                if (p < POOL) {
                    float v = sims[p];
                    if (v > best) { best = v; bi = p; }
                }
            }
            #pragma unroll
            for (int o = 16; o > 0; o >>= 1) {
                float ov = __shfl_xor_sync(0xFFFFFFFFu, best, o);
                int   oi = __shfl_xor_sync(0xFFFFFFFFu, bi,   o);
                if (ov > best || (ov == best && oi < bi)) { best = ov; bi = oi; }
            }
            if (lane == 0) {
                d_idx[b * TOPK + k] = bi;
                sims[bi] = -3.0e38f;
            }
            __syncwarp();
        }
    }
}

// ---------------------------------------------------------------------------
// Kernel 2: fused output writer (byte-identical to R4's proven 84.0us
// version). One thread = one (row, half-slot): 2 float4 at columns c4h and
// c4h+8 of a 256B row. Every LDG/STG covers exactly 4 full 128B lines.
//   g region: out[ld,b,h,gl,:] = g_prompt[ld,gl,h,:]
//   e region: out[ld,b,h,m,:]  = pool[idx[b][m/ELEN], ld, m%ELEN, h, :]
// ---------------------------------------------------------------------------
__global__ __launch_bounds__(256) void write_out_kernel(
        const float4* __restrict__ g4,
        const float4* __restrict__ pool4,
        float4* __restrict__ out4) {
    int gid = blockIdx.x * blockDim.x + threadIdx.x;
    if (gid >= TOTAL_PAIRS) return;

    const int c4h = gid & 7;       // half-slot 0..7
    const int row = gid >> 3;      // output row (256B granule)

    const float4* src;
    if (row < G_ROWS) {
        int v  = row;
        int gl = v % GLEN; v /= GLEN;
        int h  = v % H;    v /= H;
        v >>= 7;                              // drop b
        int ld = v;                           // 0..11
        src = &g4[(((ld * GLEN + gl) * H + h) << 4) + c4h];
    } else {
        int v  = row - G_ROWS;
        int m  = v % (TOPK * ELEN); v /= (TOPK * ELEN);
        int h  = v % H;             v /= H;
        int b  = v & 127;           v >>= 7;
        int ld = v;                           // 0..11
        int k  = m / ELEN;
        int e  = m - k * ELEN;
        int p  = __ldg(&d_idx[b * TOPK + k]);
        src = &pool4[((((p * 12 + ld) * ELEN + e) * H + h) << 4) + c4h];
    }

    float4 v0 = __ldg(src);
    float4 v1 = __ldg(src + 8);

    float4* dst = out4 + ((long long)row << 4) + c4h;
    __stcs(dst,     v0);
    __stcs(dst + 8, v1);
}

// ---------------------------------------------------------------------------
extern "C" void kernel_launch(void* const* d_in, const int* in_sizes, int n_in,
                              void* d_out, int out_size) {
    const float* query = (const float*)d_in[0];
    const float* gprm  = (const float*)d_in[1];
    const float* pool  = (const float*)d_in[2];
    const float* keys  = (const float*)d_in[3];
    float* out = (float*)d_out;

    // 1. top-k selection (latency-optimized)
    select_topk_kernel<<<B, 1024>>>((const float4*)query, (const float4*)keys);

    // 2. fused g + e writer (depends on d_idx; same stream => ordered)
    {
        const int threads = 256;
        int blocks = (TOTAL_PAIRS + threads - 1) / threads;   // 60,480
        write_out_kernel<<<blocks, threads>>>((const float4*)gprm,
                                              (const float4*)pool,
                                              (float4*)out);
    }
}